// round 3
// baseline (speedup 1.0000x reference)
#include <cuda_runtime.h>
#include <math.h>
#include <float.h>

// Problem dims
#define LL 64
#define BB 128
#define EE 512
#define HH 256
#define H4 1024
#define DD 512      // 2H
#define NG 2048     // fused gate dim (both directions)
#define NROWS 16384 // 2 sentences * L * B

// ---------------- scratch (device globals; no allocation allowed) ----------
__device__ float g_x[2 * LL * BB * EE];          // embedded inputs  (33.5 MB)
__device__ float g_xg[(size_t)2 * LL * BB * NG]; // input-gate GEMM out (134 MB)
__device__ float g_o[2 * LL * BB * DD];          // o1, o2 outputs (L,B,D) (33.5 MB)
__device__ float g_h[2 * 4 * BB * HH];           // double-buffered h state (1 MB)
__device__ float g_mp1[BB * DD];
__device__ float g_attsm[BB * LL];
__device__ unsigned g_sync;
__device__ unsigned g_done;

// ---------------- kernel 0: zero h state ----------------
__global__ void zero_h_kernel() {
    int i = blockIdx.x * blockDim.x + threadIdx.x;
    if (i < 2 * 4 * BB * HH) g_h[i] = 0.0f;
}

// ---------------- kernel 1: embedding gather ----------------
// g_x[s][l*B+b][:] = emb[tokens_s[l*B+b]][:]
__global__ void gather_kernel(const int* __restrict__ t1, const int* __restrict__ t2,
                              const float* __restrict__ emb) {
    int row = blockIdx.x;            // 0..16383
    int s   = row >> 13;             // 0 or 1 (8192 rows per sentence)
    int r   = row & 8191;
    int tok = s ? t2[r] : t1[r];
    const float4* src = (const float4*)(emb + (size_t)tok * EE);
    float4* dst = (float4*)(g_x + (size_t)row * EE);
    int tid = threadIdx.x;           // 128 threads, 128 float4 per row
    dst[tid] = src[tid];
}

// ---------------- kernel 2: input projection GEMM ----------------
// C[row][n] = sum_k g_x[row][k] * W[n][k] + bias[n]
// W = concat(Wih_f, Wih_b) rows; bias = bih+bhh per direction.
// BM=128, BN=64, BK=16, 256 threads, thread tile 8x4.
__global__ __launch_bounds__(256) void gemm_kernel(
    const float* __restrict__ Wf, const float* __restrict__ Wb,
    const float* __restrict__ bihf, const float* __restrict__ bhhf,
    const float* __restrict__ bihb, const float* __restrict__ bhhb) {
    __shared__ float As[16][132];
    __shared__ float Bs[16][68];

    int bm = blockIdx.x;             // 0..127  (M tiles)
    int bn = blockIdx.y;             // 0..31   (N tiles)
    int n0 = bn * 64;
    int dirb = (n0 >= 1024) ? 1 : 0;
    const float* W = dirb ? Wb : Wf;
    int nW0 = dirb ? (n0 - 1024) : n0;

    const float* A = g_x + (size_t)bm * 128 * EE;
    int tid = threadIdx.x;
    int tr = tid >> 4;               // 0..15 -> 8 rows each
    int tc = tid & 15;               // 0..15 -> 4 cols each

    float acc[8][4];
#pragma unroll
    for (int i = 0; i < 8; i++)
#pragma unroll
        for (int j = 0; j < 4; j++) acc[i][j] = 0.0f;

    for (int k0 = 0; k0 < EE; k0 += 16) {
        // load A tile (128 x 16) transposed into smem
#pragma unroll
        for (int i = 0; i < 2; i++) {
            int idx = tid + 256 * i;     // 512 float4
            int ar = idx >> 2, k4 = idx & 3;
            float4 v = *(const float4*)(A + (size_t)ar * EE + k0 + k4 * 4);
            As[k4 * 4 + 0][ar] = v.x; As[k4 * 4 + 1][ar] = v.y;
            As[k4 * 4 + 2][ar] = v.z; As[k4 * 4 + 3][ar] = v.w;
        }
        // load W tile (64 x 16) transposed
        {
            int nr = tid >> 2, k4 = tid & 3;
            float4 v = *(const float4*)(W + (size_t)(nW0 + nr) * EE + k0 + k4 * 4);
            Bs[k4 * 4 + 0][nr] = v.x; Bs[k4 * 4 + 1][nr] = v.y;
            Bs[k4 * 4 + 2][nr] = v.z; Bs[k4 * 4 + 3][nr] = v.w;
        }
        __syncthreads();
#pragma unroll
        for (int kk = 0; kk < 16; kk++) {
            float a[8], b[4];
            *(float4*)(a)     = *(const float4*)&As[kk][tr * 8];
            *(float4*)(a + 4) = *(const float4*)&As[kk][tr * 8 + 4];
            *(float4*)(b)     = *(const float4*)&Bs[kk][tc * 4];
#pragma unroll
            for (int i = 0; i < 8; i++)
#pragma unroll
                for (int j = 0; j < 4; j++)
                    acc[i][j] = fmaf(a[i], b[j], acc[i][j]);
        }
        __syncthreads();
    }

    // bias + store
    float bs[4];
#pragma unroll
    for (int j = 0; j < 4; j++) {
        int n = n0 + tc * 4 + j;
        bs[j] = dirb ? (bihb[n - 1024] + bhhb[n - 1024]) : (bihf[n] + bhhf[n]);
    }
#pragma unroll
    for (int i = 0; i < 8; i++) {
        int row = bm * 128 + tr * 8 + i;
        float4 v = make_float4(acc[i][0] + bs[0], acc[i][1] + bs[1],
                               acc[i][2] + bs[2], acc[i][3] + bs[3]);
        *(float4*)(g_xg + (size_t)row * NG + n0 + tc * 4) = v;
    }
}

// ---------------- kernel 3: persistent LSTM recurrence ----------------
// 128 blocks = 4 scans x 32 hidden-slices. Block: 128 batches x 8 units x 4 gates.
// Thread (256/block): ct = unit-in-slice (0..7), bt = batch tile (0..31), 4 batches.
// Whh slice cached in smem once; h double-buffered in global, restaged each step.
__device__ __forceinline__ float sigf(float x) { return 1.0f / (1.0f + expf(-x)); }

__global__ __launch_bounds__(256, 1) void lstm_kernel(const float* __restrict__ Whh_f,
                                                      const float* __restrict__ Whh_b) {
    extern __shared__ float sm[];
    float* sh_w = sm;                 // [32][260]
    float* sh_h = sm + 32 * 260;      // [128][260]

    const int tid = threadIdx.x;
    const int rec = blockIdx.x >> 5;  // 0..3 : (s1,f)(s1,b)(s2,f)(s2,b)
    const int slice = blockIdx.x & 31;
    const int s = rec >> 1;
    const int dir = rec & 1;
    const int ct = tid & 7;           // unit within slice
    const int bt = tid >> 3;          // 0..31
    const int b0 = bt * 4;
    const int j = slice * 8 + ct;     // hidden unit 0..255
    const float* Whh = dir ? Whh_b : Whh_f;

    // load Whh rows {g*256 + slice*8 + jj} -> sh_w[g*8+jj][k]
    for (int idx = tid; idx < 32 * 64; idx += 256) {
        int cl = idx >> 6;            // c_local 0..31
        int k4 = idx & 63;
        int g = cl >> 3, jj = cl & 7;
        float4 v = *(const float4*)(Whh + (size_t)(g * 256 + slice * 8 + jj) * HH + k4 * 4);
        *(float4*)(sh_w + cl * 260 + k4 * 4) = v;
    }

    float c_st[4] = {0.f, 0.f, 0.f, 0.f};

    for (int t = 0; t < 64; ++t) {
        const int l = dir ? (63 - t) : t;
        const float* hsrc = g_h + (size_t)((t & 1) * 4 + rec) * BB * HH;

        __syncthreads();  // protect sh_h reuse
        // stage h_prev (L2-only reads: L1 may be stale across the barrier)
        for (int idx = tid; idx < BB * 64; idx += 256) {
            int b = idx >> 6, k4 = idx & 63;
            float4 v = __ldcg((const float4*)(hsrc + (size_t)b * HH + k4 * 4));
            *(float4*)(sh_h + b * 260 + k4 * 4) = v;
        }

        // init acc with xg
        float acc[4][4];
        const float* xgp = g_xg + (size_t)(s * 8192 + l * 128 + b0) * NG + dir * 1024 + j;
#pragma unroll
        for (int bi = 0; bi < 4; bi++)
#pragma unroll
            for (int g = 0; g < 4; g++)
                acc[bi][g] = xgp[(size_t)bi * NG + g * 256];
        __syncthreads();

        // gates += h_prev @ Whh^T (slice)
#pragma unroll 2
        for (int k4 = 0; k4 < 64; ++k4) {
            float4 w0 = *(const float4*)(sh_w + (ct)      * 260 + k4 * 4);
            float4 w1 = *(const float4*)(sh_w + (8 + ct)  * 260 + k4 * 4);
            float4 w2 = *(const float4*)(sh_w + (16 + ct) * 260 + k4 * 4);
            float4 w3 = *(const float4*)(sh_w + (24 + ct) * 260 + k4 * 4);
#pragma unroll
            for (int bi = 0; bi < 4; bi++) {
                float4 hv = *(const float4*)(sh_h + (b0 + bi) * 260 + k4 * 4);
                acc[bi][0] = fmaf(hv.x, w0.x, acc[bi][0]);
                acc[bi][0] = fmaf(hv.y, w0.y, acc[bi][0]);
                acc[bi][0] = fmaf(hv.z, w0.z, acc[bi][0]);
                acc[bi][0] = fmaf(hv.w, w0.w, acc[bi][0]);
                acc[bi][1] = fmaf(hv.x, w1.x, acc[bi][1]);
                acc[bi][1] = fmaf(hv.y, w1.y, acc[bi][1]);
                acc[bi][1] = fmaf(hv.z, w1.z, acc[bi][1]);
                acc[bi][1] = fmaf(hv.w, w1.w, acc[bi][1]);
                acc[bi][2] = fmaf(hv.x, w2.x, acc[bi][2]);
                acc[bi][2] = fmaf(hv.y, w2.y, acc[bi][2]);
                acc[bi][2] = fmaf(hv.z, w2.z, acc[bi][2]);
                acc[bi][2] = fmaf(hv.w, w2.w, acc[bi][2]);
                acc[bi][3] = fmaf(hv.x, w3.x, acc[bi][3]);
                acc[bi][3] = fmaf(hv.y, w3.y, acc[bi][3]);
                acc[bi][3] = fmaf(hv.z, w3.z, acc[bi][3]);
                acc[bi][3] = fmaf(hv.w, w3.w, acc[bi][3]);
            }
        }

        // nonlinearity + state update + writes
        float* hdst = g_h + (size_t)(((t + 1) & 1) * 4 + rec) * BB * HH;
        float* odst = g_o + (size_t)s * LL * BB * DD + (size_t)l * BB * DD + dir * HH + j;
#pragma unroll
        for (int bi = 0; bi < 4; bi++) {
            float ig = sigf(acc[bi][0]);
            float fg = sigf(acc[bi][1]);
            float gg = tanhf(acc[bi][2]);
            float og = sigf(acc[bi][3]);
            float c = fmaf(fg, c_st[bi], ig * gg);
            c_st[bi] = c;
            float h = og * tanhf(c);
            hdst[(size_t)(b0 + bi) * HH + j] = h;
            odst[(size_t)(b0 + bi) * DD] = h;
        }

        // global barrier (monotonic counter; 128 blocks, all co-resident at 1/SM)
        if (tid == 0) {
            __threadfence();
            atomicAdd(&g_sync, 1u);
            unsigned target = 128u * (unsigned)(t + 1);
            while (*((volatile unsigned*)&g_sync) < target) { }
            __threadfence();
        }
        __syncthreads();
    }

    // self-reset for graph replays: last block out resets counters
    if (tid == 0) {
        unsigned old = atomicAdd(&g_done, 1u);
        if (old == 127u) {
            g_done = 0u;
            g_sync = 0u;
            __threadfence();
        }
    }
}

// ---------------- kernel 4: mp1 = max over time of o1 ----------------
__global__ void mp1_kernel() {
    int b = blockIdx.x;
    for (int d = threadIdx.x; d < DD; d += blockDim.x) {
        float m = -FLT_MAX;
#pragma unroll 8
        for (int l = 0; l < LL; l++)
            m = fmaxf(m, g_o[(size_t)l * BB * DD + b * DD + d]);
        g_mp1[b * DD + d] = m;
    }
}

// ---------------- kernel 5: attention + softmax (raw-reshape semantics) ----
// att[b][l] = sum_d mp1[b][d] * o2_flat[b*D*L + d*L + l]; softmax over l.
__global__ void att_kernel() {
    __shared__ float smp[DD];
    __shared__ float sat[LL];
    int b = blockIdx.x, l = threadIdx.x;   // 64 threads
    const float* o2 = g_o + (size_t)LL * BB * DD;
    for (int d = l; d < DD; d += LL) smp[d] = g_mp1[b * DD + d];
    __syncthreads();
    float a = 0.0f;
    for (int d = 0; d < DD; d++)
        a = fmaf(smp[d], o2[(size_t)b * DD * LL + d * LL + l], a);
    sat[l] = a;
    __syncthreads();
    float mx = -FLT_MAX;
    for (int i = 0; i < LL; i++) mx = fmaxf(mx, sat[i]);
    float ssum = 0.0f;
    for (int i = 0; i < LL; i++) ssum += expf(sat[i] - mx);
    g_attsm[b * LL + l] = expf(a - mx) / ssum;
}

// ---------------- kernel 6: new_pool + sim (fused) ----------------
// np[b][d] = sum_l att_sm[b][l] * o2_flat[b*L*D + l*D + d];
// sim[b] = exp(-sum_d |mp1 - np|)
__global__ void sim_kernel(float* __restrict__ out) {
    __shared__ float sal[LL];
    __shared__ float red[256];
    int b = blockIdx.x, tid = threadIdx.x;
    if (tid < LL) sal[tid] = g_attsm[b * LL + tid];
    __syncthreads();
    const float* o2 = g_o + (size_t)LL * BB * DD;
    float local = 0.0f;
    for (int d = tid; d < DD; d += 256) {
        float np = 0.0f;
#pragma unroll 8
        for (int l = 0; l < LL; l++)
            np = fmaf(sal[l], o2[(size_t)b * LL * DD + l * DD + d], np);
        local += fabsf(g_mp1[b * DD + d] - np);
    }
    red[tid] = local;
    __syncthreads();
    for (int s2 = 128; s2 > 0; s2 >>= 1) {
        if (tid < s2) red[tid] += red[tid + s2];
        __syncthreads();
    }
    if (tid == 0) out[b] = expf(-red[0]);
}

// ---------------- kernel 7: commonWords + e1h/e2h ----------------
__global__ void e_kernel(const int* __restrict__ t1, const int* __restrict__ t2,
                         float* __restrict__ out) {
    __shared__ int s1[LL];
    __shared__ int spos[LL];
    __shared__ int smask[LL];
    __shared__ int shas;
    int b = blockIdx.x, tid = threadIdx.x;
    if (tid == 0) shas = 0;
    if (tid < LL) s1[tid] = t1[tid * BB + b];
    __syncthreads();
    if (tid < LL) {
        int tok2 = t2[tid * BB + b];
        int d = -1;
        for (int jj = 0; jj < LL; jj++)
            if (s1[jj] == tok2) d = jj;
        int m = (d > 1) && (tok2 > 0);
        smask[tid] = m;
        spos[tid] = min(max(d, 0), LL - 1);
        if (m) atomicOr(&shas, 1);
    }
    __syncthreads();
    int has = shas;
    const float* o1 = g_o;
    const float* o2 = g_o + (size_t)LL * BB * DD;
    for (int d = tid; d < DD; d += 256) {
        float m1 = -FLT_MAX, m2 = -FLT_MAX;
        for (int i = 0; i < LL; i++) {
            if (smask[i]) {
                m1 = fmaxf(m1, o1[(size_t)spos[i] * BB * DD + b * DD + d]);
                m2 = fmaxf(m2, o2[(size_t)i * BB * DD + b * DD + d]);
            }
        }
        out[128 + b * DD + d] = has ? m1 : 0.0f;
        out[128 + BB * DD + b * DD + d] = has ? m2 : 0.0f;
    }
}

// ---------------- launch ----------------
extern "C" void kernel_launch(void* const* d_in, const int* in_sizes, int n_in,
                              void* d_out, int out_size) {
    const int* t1 = (const int*)d_in[0];
    const int* t2 = (const int*)d_in[1];
    const float* emb = (const float*)d_in[2];
    const float* Wihf = (const float*)d_in[3];
    const float* Whhf = (const float*)d_in[4];
    const float* bihf = (const float*)d_in[5];
    const float* bhhf = (const float*)d_in[6];
    const float* Wihb = (const float*)d_in[7];
    const float* Whhb = (const float*)d_in[8];
    const float* bihb = (const float*)d_in[9];
    const float* bhhb = (const float*)d_in[10];
    float* out = (float*)d_out;

    zero_h_kernel<<<(2 * 4 * BB * HH + 255) / 256, 256>>>();
    gather_kernel<<<NROWS, 128>>>(t1, t2, emb);

    dim3 ggrid(128, 32);
    gemm_kernel<<<ggrid, 256>>>(Wihf, Wihb, bihf, bhhf, bihb, bhhb);

    const int lstm_smem = (32 * 260 + 128 * 260) * 4;  // 166,400 B
    cudaFuncSetAttribute(lstm_kernel, cudaFuncAttributeMaxDynamicSharedMemorySize, lstm_smem);
    lstm_kernel<<<128, 256, lstm_smem>>>(Whhf, Whhb);

    mp1_kernel<<<BB, 128>>>();
    att_kernel<<<BB, LL>>>();
    sim_kernel<<<BB, 256>>>(out);
    e_kernel<<<BB, 256>>>(t1, t2, out);
}